// round 2
// baseline (speedup 1.0000x reference)
#include <cuda_runtime.h>

#define NV 5
#define NB 2
#define NC 32
#define NH 256
#define NW 320
#define HW (NH*NW)
#define CN 4
#define WPB 8   // warps per block in main kernel

// Per (b, view-1): 9 rotation + 3 translation floats of proj_i @ inv(proj_0)
__device__ float g_proj[NB*(NV-1)*12];
// NHWC-transposed features: [img = v*NB+b][h*W+w][c]
__device__ float g_featT[(size_t)NV*NB*HW*NC];

__global__ void setup_proj_kernel(const float* __restrict__ pm) {
    int t = threadIdx.x;
    if (t >= NB*(NV-1)) return;
    int b  = t / (NV-1);
    int vi = t % (NV-1) + 1;

    double M0[3][3], m0[3], Mi[3][3], mi[3];
    for (int which = 0; which < 2; which++) {
        int v = (which == 0) ? 0 : vi;
        const float* E = pm + ((size_t)(b*NV + v)*2 + 0)*16;
        const float* K = pm + ((size_t)(b*NV + v)*2 + 1)*16;
        double (*M)[3] = (which == 0) ? M0 : Mi;
        double *m      = (which == 0) ? m0 : mi;
        for (int r = 0; r < 3; r++) {
            for (int c = 0; c < 3; c++) {
                double s = 0;
                for (int k = 0; k < 3; k++) s += (double)K[r*4+k] * (double)E[k*4+c];
                M[r][c] = s;
            }
            double s = 0;
            for (int k = 0; k < 3; k++) s += (double)K[r*4+k] * (double)E[k*4+3];
            m[r] = s;
        }
    }
    double a00=M0[0][0],a01=M0[0][1],a02=M0[0][2];
    double a10=M0[1][0],a11=M0[1][1],a12=M0[1][2];
    double a20=M0[2][0],a21=M0[2][1],a22=M0[2][2];
    double det = a00*(a11*a22-a12*a21) - a01*(a10*a22-a12*a20) + a02*(a10*a21-a11*a20);
    double id = 1.0/det;
    double I[3][3];
    I[0][0]=(a11*a22-a12*a21)*id; I[0][1]=(a02*a21-a01*a22)*id; I[0][2]=(a01*a12-a02*a11)*id;
    I[1][0]=(a12*a20-a10*a22)*id; I[1][1]=(a00*a22-a02*a20)*id; I[1][2]=(a02*a10-a00*a12)*id;
    I[2][0]=(a10*a21-a11*a20)*id; I[2][1]=(a01*a20-a00*a21)*id; I[2][2]=(a00*a11-a01*a10)*id;

    double R[3][3], tv[3];
    for (int r = 0; r < 3; r++)
        for (int c = 0; c < 3; c++) {
            double s = 0;
            for (int k = 0; k < 3; k++) s += Mi[r][k]*I[k][c];
            R[r][c] = s;
        }
    for (int r = 0; r < 3; r++) {
        double s = 0;
        for (int k = 0; k < 3; k++) s += R[r][k]*m0[k];
        tv[r] = mi[r] - s;
    }
    float* o = g_proj + t*12;
    o[0]=(float)R[0][0]; o[1]=(float)R[0][1]; o[2]=(float)R[0][2];
    o[3]=(float)R[1][0]; o[4]=(float)R[1][1]; o[5]=(float)R[1][2];
    o[6]=(float)R[2][0]; o[7]=(float)R[2][1]; o[8]=(float)R[2][2];
    o[9]=(float)tv[0]; o[10]=(float)tv[1]; o[11]=(float)tv[2];
}

// CHW -> HWC transpose, 32x32 tiles. block (32,8), grid (HW/32, NV*NB)
__global__ void __launch_bounds__(256)
transpose_kernel(const float* __restrict__ feat) {
    __shared__ float t[32][33];
    int img = blockIdx.y;
    int hw0 = blockIdx.x * 32;
    const float* src = feat + (size_t)img*NC*HW;
    float* dst = g_featT + (size_t)img*HW*NC;
#pragma unroll
    for (int j = 0; j < 4; j++) {
        int c = threadIdx.y + 8*j;
        t[c][threadIdx.x] = src[(size_t)c*HW + hw0 + threadIdx.x];
    }
    __syncthreads();
#pragma unroll
    for (int j = 0; j < 4; j++) {
        int r = threadIdx.y + 8*j;
        dst[(size_t)(hw0 + r)*NC + threadIdx.x] = t[threadIdx.x][r];
    }
}

// One warp per 32 consecutive pixels. Lane split: corner = lane>>3, quad = lane&7.
__global__ void __launch_bounds__(256)
getcost_kernel(const float* __restrict__ dvals,
               const float* __restrict__ dint,
               const float* __restrict__ vwts,
               float* __restrict__ out)
{
    __shared__ float sproj[NB*(NV-1)*12];
    __shared__ float tileBuf[WPB][32][CN];

    int tid = threadIdx.x;
    for (int i = tid; i < NB*(NV-1)*12; i += 256) sproj[i] = g_proj[i];
    __syncthreads();

    int wip  = tid >> 5;
    int lane = tid & 31;
    int corner = lane >> 3;
    int q      = lane & 7;
    float fdx = (float)(corner & 1);
    float fdy = (float)(corner >> 1);

    int gw   = blockIdx.x * WPB + wip;
    int pix0 = gw * 32;
    int b  = pix0 / HW;
    int p0 = pix0 - b*HW;
    int yy = p0 / NW;
    int xx0 = p0 - yy*NW;
    float fy = (float)yy;

    // per-pixel scalars: lane i holds pixel i of the tile
    float dv_l = __ldg(dvals + pix0 + lane);
    float di_l = __ldg(dint  + pix0 + lane);
    float vw_l[NV-1];
#pragma unroll
    for (int j = 0; j < NV-1; j++)
        vw_l[j] = __ldg(vwts + (size_t)(b*(NV-1)+j)*HW + p0 + lane);

    const float* refT = g_featT + (size_t)b*HW*NC;   // view 0, batch b
    const unsigned FULL = 0xffffffffu;
    const float* PRb = sproj + b*(NV-1)*12;

    for (int i = 0; i < 32; i++) {
        int p = p0 + i;
        float fx = (float)(xx0 + i);

        float invd = 1.0f / __shfl_sync(FULL, dv_l, i);
        float itv  = __shfl_sync(FULL, di_l, i);
        float low  = invd - (CN*0.5f)*itv;
        float step = (CN*itv) * (1.0f/(CN-1));
        float z[CN];
#pragma unroll
        for (int d = 0; d < CN; d++) z[d] = 1.0f/(low + (float)d*step);

        float4 r4 = __ldg((const float4*)(refT + (size_t)p*NC) + q);

        float acc[CN] = {0.f,0.f,0.f,0.f};
        float wsum = 1e-5f;

#pragma unroll
        for (int vi = 1; vi < NV; vi++) {
            const float* PR = PRb + (vi-1)*12;
            float u0 = PR[0]*fx + PR[1]*fy + PR[2];
            float u1 = PR[3]*fx + PR[4]*fy + PR[5];
            float u2 = PR[6]*fx + PR[7]*fy + PR[8];
            float t0 = PR[9], t1 = PR[10], t2 = PR[11];
            float vw = __shfl_sync(FULL, vw_l[vi-1], i);
            const float* vp = g_featT + (size_t)(vi*NB + b)*HW*NC;

#pragma unroll
            for (int d = 0; d < CN; d++) {
                float zz = z[d];
                float rz = 1.0f / (u2*zz + t2);
                float gx = (u0*zz + t0)*rz;
                float gy = (u1*zz + t1)*rz;
                float x0f = floorf(gx), y0f = floorf(gy);
                float wx = gx - x0f, wy = gy - y0f;
                float cx = x0f + fdx;
                float cy = y0f + fdy;
                bool valid = (cx >= 0.f) && (cx <= (float)(NW-1)) &&
                             (cy >= 0.f) && (cy <= (float)(NH-1));
                int xi = (int)fminf(fmaxf(cx, 0.f), (float)(NW-1));
                int yi = (int)fminf(fmaxf(cy, 0.f), (float)(NH-1));
                float wxk = (corner & 1) ? wx : 1.f - wx;
                float wyk = (corner >> 1) ? wy : 1.f - wy;
                float wgt = valid ? wxk*wyk : 0.f;
                float4 f4 = __ldg((const float4*)(vp + (size_t)(yi*NW + xi)*NC) + q);
                float dot = r4.x*f4.x + r4.y*f4.y + r4.z*f4.z + r4.w*f4.w;
                acc[d] = fmaf(vw*wgt, dot, acc[d]);
            }
            wsum += vw;
        }

        // sum over lanes (corners x channel-quads)
#pragma unroll
        for (int d = 0; d < CN; d++) {
#pragma unroll
            for (int off = 16; off >= 1; off >>= 1)
                acc[d] += __shfl_xor_sync(FULL, acc[d], off);
        }
        float scale = 1.0f/((float)NC * wsum);
        if (lane < CN) tileBuf[wip][i][lane] = acc[lane]*scale;
    }
    __syncwarp();

    // coalesced store: 128 warp-STGs of 32 consecutive floats
    float* ob = out + (size_t)b*NC*CN*HW + p0;
#pragma unroll
    for (int d = 0; d < CN; d++) {
        float val = tileBuf[wip][lane][d];
#pragma unroll 8
        for (int c = 0; c < NC; c++)
            ob[(size_t)(c*CN + d)*HW + lane] = val;
    }
}

extern "C" void kernel_launch(void* const* d_in, const int* in_sizes, int n_in,
                              void* d_out, int out_size) {
    const float *feat = nullptr, *projm = nullptr, *vw = nullptr;
    const float *dv = nullptr, *di = nullptr;
    const int sz_feat = NV*NB*NC*HW;
    const int sz_proj = NB*NV*2*16;
    const int sz_vw   = NB*(NV-1)*HW;
    const int sz_map  = NB*HW;
    for (int i = 0; i < n_in; i++) {
        int s = in_sizes[i];
        if (s == sz_feat)            feat  = (const float*)d_in[i];
        else if (s == sz_proj)       projm = (const float*)d_in[i];
        else if (s == sz_vw)         vw    = (const float*)d_in[i];
        else if (s == sz_map) {
            if (!dv) dv = (const float*)d_in[i];
            else if (!di) di = (const float*)d_in[i];
        }
    }
    float* out = (float*)d_out;

    transpose_kernel<<<dim3(HW/32, NV*NB), dim3(32, 8)>>>(feat);
    setup_proj_kernel<<<1, 32>>>(projm);
    getcost_kernel<<<(NB*HW)/(32*WPB), 256>>>(dv, di, vw, out);
}

// round 3
// speedup vs baseline: 2.4853x; 2.4853x over previous
#include <cuda_runtime.h>

#define NV 5
#define NB 2
#define NC 32
#define NH 256
#define NW 320
#define HW (NH*NW)
#define CN 4
#define CCH 8   // channel chunk

// Per (b, view-1): 9 rotation + 3 translation floats of proj_i @ inv(proj_0)
__device__ float g_proj[NB*(NV-1)*12];

__global__ void setup_proj_kernel(const float* __restrict__ pm) {
    int t = threadIdx.x;
    if (t >= NB*(NV-1)) return;
    int b  = t / (NV-1);
    int vi = t % (NV-1) + 1;

    double M0[3][3], m0[3], Mi[3][3], mi[3];
    for (int which = 0; which < 2; which++) {
        int v = (which == 0) ? 0 : vi;
        const float* E = pm + ((size_t)(b*NV + v)*2 + 0)*16;
        const float* K = pm + ((size_t)(b*NV + v)*2 + 1)*16;
        double (*M)[3] = (which == 0) ? M0 : Mi;
        double *m      = (which == 0) ? m0 : mi;
        for (int r = 0; r < 3; r++) {
            for (int c = 0; c < 3; c++) {
                double s = 0;
                for (int k = 0; k < 3; k++) s += (double)K[r*4+k] * (double)E[k*4+c];
                M[r][c] = s;
            }
            double s = 0;
            for (int k = 0; k < 3; k++) s += (double)K[r*4+k] * (double)E[k*4+3];
            m[r] = s;
        }
    }
    double a00=M0[0][0],a01=M0[0][1],a02=M0[0][2];
    double a10=M0[1][0],a11=M0[1][1],a12=M0[1][2];
    double a20=M0[2][0],a21=M0[2][1],a22=M0[2][2];
    double det = a00*(a11*a22-a12*a21) - a01*(a10*a22-a12*a20) + a02*(a10*a21-a11*a20);
    double id = 1.0/det;
    double I[3][3];
    I[0][0]=(a11*a22-a12*a21)*id; I[0][1]=(a02*a21-a01*a22)*id; I[0][2]=(a01*a12-a02*a11)*id;
    I[1][0]=(a12*a20-a10*a22)*id; I[1][1]=(a00*a22-a02*a20)*id; I[1][2]=(a02*a10-a00*a12)*id;
    I[2][0]=(a10*a21-a11*a20)*id; I[2][1]=(a01*a20-a00*a21)*id; I[2][2]=(a00*a11-a01*a10)*id;

    double R[3][3], tv[3];
    for (int r = 0; r < 3; r++)
        for (int c = 0; c < 3; c++) {
            double s = 0;
            for (int k = 0; k < 3; k++) s += Mi[r][k]*I[k][c];
            R[r][c] = s;
        }
    for (int r = 0; r < 3; r++) {
        double s = 0;
        for (int k = 0; k < 3; k++) s += R[r][k]*m0[k];
        tv[r] = mi[r] - s;
    }
    float* o = g_proj + t*12;
    o[0]=(float)R[0][0]; o[1]=(float)R[0][1]; o[2]=(float)R[0][2];
    o[3]=(float)R[1][0]; o[4]=(float)R[1][1]; o[5]=(float)R[1][2];
    o[6]=(float)R[2][0]; o[7]=(float)R[2][1]; o[8]=(float)R[2][2];
    o[9]=(float)tv[0]; o[10]=(float)tv[1]; o[11]=(float)tv[2];
}

__global__ void __launch_bounds__(256, 4)
getcost_kernel(const float* __restrict__ feat,
               const float* __restrict__ dvals,
               const float* __restrict__ dint,
               const float* __restrict__ vwts,
               float* __restrict__ out)
{
    __shared__ float sproj[NB*(NV-1)*12];
    for (int i = threadIdx.x; i < NB*(NV-1)*12; i += 256) sproj[i] = g_proj[i];
    __syncthreads();

    int pix = blockIdx.x * 256 + threadIdx.x;
    int b = pix / HW;
    int p = pix - b*HW;
    int yy = p / NW;
    int xx = p - yy*NW;
    float fx = (float)xx, fy = (float)yy;

    float invd = __frcp_rn(dvals[pix]);
    float itv  = dint[pix];
    float low  = invd - (CN*0.5f)*itv;
    float step = (CN * itv) * (1.0f/(CN-1));

    float z[CN];
#pragma unroll
    for (int d = 0; d < CN; d++) z[d] = __frcp_rn(low + (float)d*step);

    float vwr[NV-1];
#pragma unroll
    for (int j = 0; j < NV-1; j++)
        vwr[j] = __ldg(vwts + ((size_t)(b*(NV-1)+j))*HW + p);

    float vol[CN] = {0.f,0.f,0.f,0.f};
    float wsum = 1e-5f;
#pragma unroll
    for (int j = 0; j < NV-1; j++) wsum += vwr[j];

    const float* rbase = feat + (size_t)b*NC*HW + p;
    const float* PRb = sproj + b*(NV-1)*12;

    for (int cc = 0; cc < NC/CCH; cc++) {
        float ref[CCH];
#pragma unroll
        for (int j = 0; j < CCH; j++)
            ref[j] = __ldg(rbase + (size_t)(cc*CCH + j)*HW);

#pragma unroll
        for (int vi = 1; vi < NV; vi++) {
            const float* PR = PRb + (vi-1)*12;
            float u0 = PR[0]*fx + PR[1]*fy + PR[2];
            float u1 = PR[3]*fx + PR[4]*fy + PR[5];
            float u2 = PR[6]*fx + PR[7]*fy + PR[8];
            float t0 = PR[9], t1 = PR[10], t2 = PR[11];
            float vw = vwr[vi-1];
            const float* fb = feat + (size_t)(vi*NB + b)*NC*HW + (size_t)cc*CCH*HW;

#pragma unroll
            for (int d = 0; d < CN; d++) {
                float zz = z[d];
                float pz = u2*zz + t2;
                float gx = __fdividef(u0*zz + t0, pz);
                float gy = __fdividef(u1*zz + t1, pz);
                float x0f = floorf(gx), y0f = floorf(gy);
                float wx = gx - x0f, wy = gy - y0f;
                float x1f = x0f + 1.0f, y1f = y0f + 1.0f;

                bool vx0 = (x0f >= 0.f) && (x0f <= (float)(NW-1));
                bool vx1 = (x1f >= 0.f) && (x1f <= (float)(NW-1));
                bool vy0 = (y0f >= 0.f) && (y0f <= (float)(NH-1));
                bool vy1 = (y1f >= 0.f) && (y1f <= (float)(NH-1));

                int xi0 = (int)fminf(fmaxf(x0f, 0.f), (float)(NW-1));
                int xi1 = (int)fminf(fmaxf(x1f, 0.f), (float)(NW-1));
                int yi0 = (int)fminf(fmaxf(y0f, 0.f), (float)(NH-1));
                int yi1 = (int)fminf(fmaxf(y1f, 0.f), (float)(NH-1));

                int i0 = yi0*NW + xi0;
                int i1 = yi0*NW + xi1;
                int i2 = yi1*NW + xi0;
                int i3 = yi1*NW + xi1;

                float iwx = 1.0f - wx, iwy = 1.0f - wy;
                float w0 = (vx0 && vy0) ? iwx*iwy : 0.f;
                float w1 = (vx1 && vy0) ? wx*iwy  : 0.f;
                float w2 = (vx0 && vy1) ? iwx*wy  : 0.f;
                float w3 = (vx1 && vy1) ? wx*wy   : 0.f;

                float S0 = 0.f, S1 = 0.f, S2 = 0.f, S3 = 0.f;
#pragma unroll
                for (int j = 0; j < CCH; j++) {
                    const float* fc = fb + (size_t)j*HW;
                    float r = ref[j];
                    S0 = fmaf(r, __ldg(fc + i0), S0);
                    S1 = fmaf(r, __ldg(fc + i1), S1);
                    S2 = fmaf(r, __ldg(fc + i2), S2);
                    S3 = fmaf(r, __ldg(fc + i3), S3);
                }
                float val = w0*S0 + w1*S1 + w2*S2 + w3*S3;
                vol[d] = fmaf(vw, val, vol[d]);
            }
        }
    }

    float scale = __frcp_rn((float)NC * wsum);
#pragma unroll
    for (int d = 0; d < CN; d++) {
        float sim = vol[d] * scale;
        float* ob = out + ((size_t)b*NC*CN + d)*HW + p;
#pragma unroll 8
        for (int c = 0; c < NC; c++) ob[(size_t)c*CN*HW] = sim;
    }
}

extern "C" void kernel_launch(void* const* d_in, const int* in_sizes, int n_in,
                              void* d_out, int out_size) {
    const float *feat = nullptr, *projm = nullptr, *vw = nullptr;
    const float *dv = nullptr, *di = nullptr;
    const int sz_feat = NV*NB*NC*HW;
    const int sz_proj = NB*NV*2*16;
    const int sz_vw   = NB*(NV-1)*HW;
    const int sz_map  = NB*HW;
    for (int i = 0; i < n_in; i++) {
        int s = in_sizes[i];
        if (s == sz_feat)            feat  = (const float*)d_in[i];
        else if (s == sz_proj)       projm = (const float*)d_in[i];
        else if (s == sz_vw)         vw    = (const float*)d_in[i];
        else if (s == sz_map) {
            if (!dv) dv = (const float*)d_in[i];
            else if (!di) di = (const float*)d_in[i];
        }
    }
    float* out = (float*)d_out;

    setup_proj_kernel<<<1, 32>>>(projm);
    getcost_kernel<<<(NB*HW)/256, 256>>>(feat, dv, di, vw, out);
}